// round 11
// baseline (speedup 1.0000x reference)
#include <cuda_runtime.h>
#include <math.h>
#include <stdint.h>

#define B_   8
#define N_   2048
#define M_   512
#define C_   256
#define NR_  4
#define CNT_ (B_*NR_*N_)

// ---------------- scratch ----------------
__device__ float g_G [B_*NR_*M_*C_];   // [z][m][o] o-contiguous
__device__ float g_y1[B_*NR_*C_*N_];   // [z][c][n] n-contiguous
__device__ int   g_idx[B_*N_*3];
__device__ float g_w  [B_*N_*3];
__device__ float g_s1[C_], g_q1[C_], g_s2[C_], g_q2[C_];
__device__ float g_scale1[C_], g_bias1[C_], g_scale2[C_], g_bias2[C_];

// ---------------- helpers ----------------
__device__ __forceinline__ unsigned f2tf(float f) {
    unsigned u; asm("cvt.rna.tf32.f32 %0, %1;" : "=r"(u) : "f"(f)); return u;
}
__device__ __forceinline__ void mma8(float* c, const unsigned* a, const unsigned* b) {
    asm volatile("mma.sync.aligned.m16n8k8.row.col.f32.tf32.tf32.f32 "
        "{%0,%1,%2,%3}, {%4,%5,%6,%7}, {%8,%9}, {%0,%1,%2,%3};"
        : "+f"(c[0]), "+f"(c[1]), "+f"(c[2]), "+f"(c[3])
        : "r"(a[0]), "r"(a[1]), "r"(a[2]), "r"(a[3]), "r"(b[0]), "r"(b[1]));
}
__device__ __forceinline__ void cp16(float* dst, const float* src) {
    uint32_t d;
    asm("{ .reg .u64 t; cvta.to.shared.u64 t, %1; cvt.u32.u64 %0, t; }" : "=r"(d) : "l"(dst));
    asm volatile("cp.async.ca.shared.global [%0], [%1], 16;" :: "r"(d), "l"(src) : "memory");
}
#define CP_COMMIT() asm volatile("cp.async.commit_group;" ::: "memory")
#define CP_WAIT(n)  asm volatile("cp.async.wait_group %0;" :: "n"(n) : "memory")

// ---------------- smem layout (floats) ----------------
#define AP 20                  // A stage pitch: 16 k + 4 pad
#define BP 136                 // B stage pitch: 128 n + 8 pad
#define YP 257                 // Ys pitch (odd -> scalar passes conflict-free)
#define STGF 7296              // stage stride: A 256*20=5120 + B 16*136=2176
#define OFF_B 5120
#define NSTG 4                 // 4-stage ring: 29184 floats, aliased by Ys below
#define OFF_S (128*257)        // 32896 : stats sum (256)
#define OFF_Q (OFF_S + 256)
#define OFF_W (OFF_Q + 256)    // interp weights (384)
#define OFF_I (OFF_W + 384)    // interp indices (384, int view)
#define SMEMF (OFF_I + 384)    // 34176 floats = 136704 bytes
#define SMEM_BYTES (SMEMF * 4)

// ---------------- small kernels ----------------
__global__ void zero_stats_kernel() {
    int t = threadIdx.x;
    g_s1[t] = 0.f; g_q1[t] = 0.f; g_s2[t] = 0.f; g_q2[t] = 0.f;
}

__global__ void knn_kernel(const float* __restrict__ unknown,
                           const float* __restrict__ known) {
    __shared__ float ks[M_*3];
    int b = blockIdx.y;
    const float* kb = known + (size_t)b * M_ * 3;
    for (int i = threadIdx.x; i < M_*3; i += blockDim.x) ks[i] = kb[i];
    __syncthreads();
    int n = blockIdx.x * blockDim.x + threadIdx.x;
    const float* u = unknown + ((size_t)b * N_ + n) * 3;
    float ux = u[0], uy = u[1], uz = u[2];
    float d0 = 3.4e38f, d1 = 3.4e38f, d2 = 3.4e38f;
    int   i0 = 0, i1 = 0, i2 = 0;
    for (int m = 0; m < M_; m++) {
        float dx = ux - ks[m*3], dy = uy - ks[m*3+1], dz = uz - ks[m*3+2];
        float d  = dx*dx + dy*dy + dz*dz;
        if (d < d2) {
            if (d < d0)      { d2=d1; i2=i1; d1=d0; i1=i0; d0=d; i0=m; }
            else if (d < d1) { d2=d1; i2=i1; d1=d;  i1=m; }
            else             { d2=d;  i2=m; }
        }
    }
    float r0 = 1.f / (sqrtf(fmaxf(d0, 0.f)) + 1e-8f);
    float r1 = 1.f / (sqrtf(fmaxf(d1, 0.f)) + 1e-8f);
    float r2 = 1.f / (sqrtf(fmaxf(d2, 0.f)) + 1e-8f);
    float inv = 1.f / (r0 + r1 + r2);
    int base = (b * N_ + n) * 3;
    g_idx[base] = i0; g_idx[base+1] = i1; g_idx[base+2] = i2;
    g_w[base] = r0*inv; g_w[base+1] = r1*inv; g_w[base+2] = r2*inv;
}

__global__ void bnfin_kernel(const float* __restrict__ gamma,
                             const float* __restrict__ beta, int which) {
    int t = threadIdx.x;
    float s = which ? g_s2[t] : g_s1[t];
    float q = which ? g_q2[t] : g_q1[t];
    float mean = s * (1.f / CNT_);
    float var  = q * (1.f / CNT_) - mean * mean;
    float sc = gamma[t] * rsqrtf(var + 1e-5f);
    float bi = beta[t] - mean * sc;
    if (which) { g_scale2[t] = sc; g_bias2[t] = bi; }
    else       { g_scale1[t] = sc; g_bias1[t] = bi; }
}

__global__ void out_kernel(float* __restrict__ out) {
    int i = blockIdx.x * blockDim.x + threadIdx.x;
    int o = (i >> 11) & 255;
    float sc = g_scale2[o], bi = g_bias2[o];
    float4 v = ((float4*)out)[i];
    v.x = fmaxf(fmaf(v.x, sc, bi), 0.f);
    v.y = fmaxf(fmaf(v.y, sc, bi), 0.f);
    v.z = fmaxf(fmaf(v.z, sc, bi), 0.f);
    v.w = fmaxf(fmaf(v.w, sc, bi), 0.f);
    ((float4*)out)[i] = v;
}

// ---------------- GEMM core ----------------
// Block tile 256(o) x 128(n), K chunk 16. 8 warps (4 o x 2 n), warp tile 64x64.
// A staged [o][AP] raw fp32 (cp.async), B staged [k][BP] raw fp32 (cp.async).
// cvt.rna on fragments. 4-stage ring, prefetch distance 3, ONE sync per chunk.

__device__ __forceinline__ void stageA(float* sm, int p, const float* Wsrc,
                                       int wstride, int c, int tid) {
    float* Ad = sm + p*STGF + tid*AP;
    const float* src = Wsrc + (size_t)tid * wstride + c*16;
    cp16(Ad, src); cp16(Ad+4, src+4); cp16(Ad+8, src+8); cp16(Ad+12, src+12);
}
__device__ __forceinline__ void stageB(float* sm, int p, const float* Xsrc,
                                       int cs, int c, int tid) {
    int k = tid >> 4, ng = (tid & 15) * 8;
    float* Bd = sm + p*STGF + OFF_B + k*BP + ng;
    const float* src = Xsrc + (size_t)(c*16 + k) * cs + ng;
    cp16(Bd, src); cp16(Bd+4, src+4);
}

__device__ __forceinline__ void frag_mma(const float* A, const float* Bs,
                                         int wo, int wn, int g, int t,
                                         float acc[4][8][4]) {
    #pragma unroll
    for (int ks = 0; ks < 16; ks += 8) {
        unsigned af[4][4], bf[8][2];
        #pragma unroll
        for (int mi = 0; mi < 4; mi++) {
            int orow = wo*64 + mi*16 + g;
            af[mi][0] = f2tf(A[orow*AP + ks + t]);
            af[mi][1] = f2tf(A[(orow+8)*AP + ks + t]);
            af[mi][2] = f2tf(A[orow*AP + ks + t + 4]);
            af[mi][3] = f2tf(A[(orow+8)*AP + ks + t + 4]);
        }
        #pragma unroll
        for (int ni = 0; ni < 8; ni++) {
            int nb = wn*64 + ni*8 + g;
            bf[ni][0] = f2tf(Bs[(ks+t)*BP + nb]);
            bf[ni][1] = f2tf(Bs[(ks+t+4)*BP + nb]);
        }
        #pragma unroll
        for (int mi = 0; mi < 4; mi++)
            #pragma unroll
            for (int ni = 0; ni < 8; ni++)
                mma8(acc[mi][ni], af[mi], bf[ni]);
    }
}

// plain mainloop (gemmG / gemmY1): 4-stage ring, 1 sync/chunk
__device__ __forceinline__ void mainloop4(float* sm, const float* Wsrc, int wstride,
                                          const float* Xsrc, int cs,
                                          float acc[4][8][4]) {
    int tid = threadIdx.x, lane = tid & 31, w = tid >> 5;
    int wo = w >> 1, wn = w & 1, g = lane >> 2, t = lane & 3;
    #pragma unroll
    for (int s = 0; s < 3; s++) {
        stageA(sm, s, Wsrc, wstride, s, tid);
        stageB(sm, s, Xsrc, cs, s, tid);
        CP_COMMIT();
    }
    for (int c = 0; c < 16; c++) {
        if (c < 14) CP_WAIT(2); else if (c == 14) CP_WAIT(1); else CP_WAIT(0);
        __syncthreads();   // all threads see stage c; all done reading stage (c-1)
        if (c + 3 < 16) {
            stageA(sm, (c+3) & 3, Wsrc, wstride, c+3, tid);
            stageB(sm, (c+3) & 3, Xsrc, cs, c+3, tid);
            CP_COMMIT();
        }
        frag_mma(sm + (c&3)*STGF, sm + (c&3)*STGF + OFF_B, wo, wn, g, t, acc);
    }
    __syncthreads();
}

__device__ __forceinline__ void acc_to_ys(float* sm, float acc[4][8][4],
                                          int wo, int wn, int g, int t) {
    #pragma unroll
    for (int mi = 0; mi < 4; mi++)
        #pragma unroll
        for (int ni = 0; ni < 8; ni++) {
            int orow = wo*64 + mi*16 + g;
            int ncol = wn*64 + ni*8 + 2*t;
            sm[ncol*YP + orow]       = acc[mi][ni][0];
            sm[(ncol+1)*YP + orow]   = acc[mi][ni][1];
            sm[ncol*YP + orow+8]     = acc[mi][ni][2];
            sm[(ncol+1)*YP + orow+8] = acc[mi][ni][3];
        }
}

// ---------------- gemmG: G[z][m][o] = W1a @ kf ----------------
__global__ __launch_bounds__(256, 1) void gemmG(const float* __restrict__ kf,
                                                const float* __restrict__ W1) {
    extern __shared__ float sm[];
    int tid = threadIdx.x, lane = tid & 31, w = tid >> 5;
    int z = blockIdx.y, b = z >> 2, r = z & 3;
    int m0 = blockIdx.x * 128;
    float acc[4][8][4] = {};
    const float* X = kf + (size_t)b * (C_*NR_*M_) + (size_t)r * M_ + m0;
    mainloop4(sm, W1, 512, X, NR_*M_, acc);
    int wo = w >> 1, wn = w & 1, g = lane >> 2, t = lane & 3;
    acc_to_ys(sm, acc, wo, wn, g, t);
    __syncthreads();
    float* Gz = g_G + ((size_t)z * M_ + m0) * C_;
    for (int it = 0; it < 16; it++) {
        int m = it*8 + w;
        #pragma unroll
        for (int j = 0; j < 8; j++) {
            int o = lane + 32*j;
            Gz[(size_t)m * C_ + o] = sm[m*YP + o];
        }
    }
}

// ---------------- gemmY1: y1[z][c][n] = W1b@uf + gather(G); BN1 stats ----------------
__global__ __launch_bounds__(256, 1) void gemmY1(const float* __restrict__ uf,
                                                 const float* __restrict__ W1) {
    extern __shared__ float sm[];
    int tid = threadIdx.x, lane = tid & 31, w = tid >> 5;
    int z = blockIdx.y, b = z >> 2, r = z & 3;
    int n0 = blockIdx.x * 128;
    for (int l = tid; l < 384; l += 256) {
        sm[OFF_W + l]         = g_w  [(b * N_ + n0) * 3 + l];
        ((int*)sm)[OFF_I + l] = g_idx[(b * N_ + n0) * 3 + l];
    }
    sm[OFF_S + tid] = 0.f; sm[OFF_Q + tid] = 0.f;
    float acc[4][8][4] = {};
    const float* X = uf + (size_t)b * (C_*NR_*N_) + (size_t)r * N_ + n0;
    mainloop4(sm, W1 + 256, 512, X, NR_*N_, acc);
    int wo = w >> 1, wn = w & 1, g = lane >> 2, t = lane & 3;
    acc_to_ys(sm, acc, wo, wn, g, t);
    __syncthreads();
    // gather + BN1 stats (warp-per-n, lane-per-o)
    const float* Gz = g_G + (size_t)z * M_ * C_;
    float s8[8] = {}, q8[8] = {};
    for (int it = 0; it < 16; it++) {
        int n = it*8 + w;
        float w0 = sm[OFF_W + n*3], w1 = sm[OFF_W + n*3+1], w2 = sm[OFF_W + n*3+2];
        const float* G0 = Gz + (size_t)((int*)sm)[OFF_I + n*3]     * C_;
        const float* G1 = Gz + (size_t)((int*)sm)[OFF_I + n*3 + 1] * C_;
        const float* G2 = Gz + (size_t)((int*)sm)[OFF_I + n*3 + 2] * C_;
        #pragma unroll
        for (int j = 0; j < 8; j++) {
            int o = lane + 32*j;
            float v = sm[n*YP + o] + w0*G0[o] + w1*G1[o] + w2*G2[o];
            sm[n*YP + o] = v;
            s8[j] += v; q8[j] += v*v;
        }
    }
    #pragma unroll
    for (int j = 0; j < 8; j++) {
        atomicAdd(&sm[OFF_S + lane + 32*j], s8[j]);
        atomicAdd(&sm[OFF_Q + lane + 32*j], q8[j]);
    }
    __syncthreads();
    atomicAdd(&g_s1[tid], sm[OFF_S + tid]);
    atomicAdd(&g_q1[tid], sm[OFF_Q + tid]);
    // store y1[z][o][n] (n-contiguous)
    float* y1z = g_y1 + (size_t)z * C_ * N_ + n0;
    for (int it = 0; it < 32; it++) {
        int o = it*8 + w;
        #pragma unroll
        for (int j = 0; j < 4; j++) {
            int n = lane + 32*j;
            y1z[(size_t)o * N_ + n] = sm[n*YP + o];
        }
    }
}

// ---------------- gemmZ: out = W2 @ relu(bn1(y1)); BN2 stats ----------------
__global__ __launch_bounds__(256, 1) void gemmZ(const float* __restrict__ W2,
                                                float* __restrict__ out) {
    extern __shared__ float sm[];
    int tid = threadIdx.x, lane = tid & 31, w = tid >> 5;
    int z = blockIdx.y, b = z >> 2, r = z & 3;
    int n0 = blockIdx.x * 128;
    sm[OFF_S + tid] = 0.f; sm[OFF_Q + tid] = 0.f;
    float acc[4][8][4] = {};
    const float* y1z = g_y1 + (size_t)z * C_ * N_ + n0;
    int wo = w >> 1, wn = w & 1, g = lane >> 2, t = lane & 3;
    int bk = tid >> 4, bn = (tid & 15) * 8;

    #pragma unroll
    for (int s = 0; s < 3; s++) {
        stageA(sm, s, W2, 256, s, tid);
        stageB(sm, s, y1z, N_, s, tid);   // raw y1
        CP_COMMIT();
    }
    for (int c = 0; c < 16; c++) {
        if (c < 14) CP_WAIT(2); else if (c == 14) CP_WAIT(1); else CP_WAIT(0);
        __syncthreads();
        if (c + 3 < 16) {
            stageA(sm, (c+3) & 3, W2, 256, c+3, tid);
            stageB(sm, (c+3) & 3, y1z, N_, c+3, tid);
            CP_COMMIT();
        }
        // in-place BN1 + ReLU on resident B chunk
        {
            float sc = g_scale1[c*16 + bk], bi = g_bias1[c*16 + bk];
            float* Bp = sm + (c&3)*STGF + OFF_B + bk*BP + bn;
            float4 va = *(float4*)Bp, vb = *(float4*)(Bp + 4);
            va.x = fmaxf(fmaf(va.x, sc, bi), 0.f); va.y = fmaxf(fmaf(va.y, sc, bi), 0.f);
            va.z = fmaxf(fmaf(va.z, sc, bi), 0.f); va.w = fmaxf(fmaf(va.w, sc, bi), 0.f);
            vb.x = fmaxf(fmaf(vb.x, sc, bi), 0.f); vb.y = fmaxf(fmaf(vb.y, sc, bi), 0.f);
            vb.z = fmaxf(fmaf(vb.z, sc, bi), 0.f); vb.w = fmaxf(fmaf(vb.w, sc, bi), 0.f);
            *(float4*)Bp = va; *(float4*)(Bp + 4) = vb;
        }
        __syncthreads();   // transform visible to all before fragment reads
        frag_mma(sm + (c&3)*STGF, sm + (c&3)*STGF + OFF_B, wo, wn, g, t, acc);
    }
    __syncthreads();

    // BN2 stats from pre-BN accumulators
    {
        float s8[8] = {}, q8[8] = {};
        #pragma unroll
        for (int mi = 0; mi < 4; mi++)
            #pragma unroll
            for (int ni = 0; ni < 8; ni++) {
                float a0 = acc[mi][ni][0], a1 = acc[mi][ni][1];
                float a2 = acc[mi][ni][2], a3 = acc[mi][ni][3];
                s8[mi*2]   += a0 + a1;  q8[mi*2]   += a0*a0 + a1*a1;
                s8[mi*2+1] += a2 + a3;  q8[mi*2+1] += a2*a2 + a3*a3;
            }
        #pragma unroll
        for (int mi = 0; mi < 4; mi++) {
            int orow = wo*64 + mi*16 + g;
            atomicAdd(&sm[OFF_S + orow],     s8[mi*2]);
            atomicAdd(&sm[OFF_Q + orow],     q8[mi*2]);
            atomicAdd(&sm[OFF_S + orow + 8], s8[mi*2+1]);
            atomicAdd(&sm[OFF_Q + orow + 8], q8[mi*2+1]);
        }
    }
    __syncthreads();
    atomicAdd(&g_s2[tid], sm[OFF_S + tid]);
    atomicAdd(&g_q2[tid], sm[OFF_Q + tid]);
    acc_to_ys(sm, acc, wo, wn, g, t);
    __syncthreads();
    float* ob = out + ((size_t)b * 256 * 4) * 2048 + (size_t)r * 2048 + n0;
    for (int it = 0; it < 32; it++) {
        int o = it*8 + w;
        #pragma unroll
        for (int j = 0; j < 4; j++) {
            int n = lane + 32*j;
            ob[(size_t)o * (4*2048) + n] = sm[n*YP + o];
        }
    }
}

// ---------------- launch ----------------
extern "C" void kernel_launch(void* const* d_in, const int* in_sizes, int n_in,
                              void* d_out, int out_size) {
    const float* unknown = (const float*)d_in[0];
    const float* known   = (const float*)d_in[1];
    const float* uf      = (const float*)d_in[2];
    const float* kf      = (const float*)d_in[3];
    const float* W1      = (const float*)d_in[4];
    const float* g1      = (const float*)d_in[5];
    const float* b1      = (const float*)d_in[6];
    const float* W2      = (const float*)d_in[7];
    const float* g2      = (const float*)d_in[8];
    const float* b2      = (const float*)d_in[9];
    float* out = (float*)d_out;

    static int inited = 0;
    if (!inited) {
        cudaFuncSetAttribute(gemmG,  cudaFuncAttributeMaxDynamicSharedMemorySize, SMEM_BYTES);
        cudaFuncSetAttribute(gemmY1, cudaFuncAttributeMaxDynamicSharedMemorySize, SMEM_BYTES);
        cudaFuncSetAttribute(gemmZ,  cudaFuncAttributeMaxDynamicSharedMemorySize, SMEM_BYTES);
        inited = 1;
    }

    zero_stats_kernel<<<1, 256>>>();
    knn_kernel<<<dim3(N_/256, B_), 256>>>(unknown, known);
    gemmG<<<dim3(M_/128, B_*NR_), 256, SMEM_BYTES>>>(kf, W1);
    gemmY1<<<dim3(N_/128, B_*NR_), 256, SMEM_BYTES>>>(uf, W1);
    bnfin_kernel<<<1, 256>>>(g1, b1, 0);
    gemmZ<<<dim3(N_/128, B_*NR_), 256, SMEM_BYTES>>>(W2, out);
    bnfin_kernel<<<1, 256>>>(g2, b2, 1);
    out_kernel<<<(B_*256*NR_*N_/4) / 256, 256>>>(out);
}

// round 13
// speedup vs baseline: 1.0552x; 1.0552x over previous
#include <cuda_runtime.h>
#include <cuda_fp16.h>
#include <math.h>
#include <stdint.h>

#define B_   8
#define N_   2048
#define M_   512
#define C_   256
#define NR_  4
#define CNT_ (B_*NR_*N_)

// ---------------- scratch ----------------
__device__ float g_G [B_*NR_*M_*C_];   // [z][m][o] o-contiguous
__device__ float g_y1[B_*NR_*C_*N_];   // [z][c][n] n-contiguous
__device__ int   g_idx[B_*N_*3];
__device__ float g_w  [B_*N_*3];
__device__ float g_s1[C_], g_q1[C_], g_s2[C_], g_q2[C_];
__device__ float g_scale1[C_], g_bias1[C_], g_scale2[C_], g_bias2[C_];

// ---------------- helpers ----------------
__device__ __forceinline__ unsigned pack2(float lo, float hi) {
    __half2 h = __floats2half2_rn(lo, hi);
    return *reinterpret_cast<unsigned*>(&h);
}
__device__ __forceinline__ void hmma16(float* c, const unsigned* a, const unsigned* b) {
    asm volatile("mma.sync.aligned.m16n8k16.row.col.f32.f16.f16.f32 "
        "{%0,%1,%2,%3}, {%4,%5,%6,%7}, {%8,%9}, {%0,%1,%2,%3};"
        : "+f"(c[0]), "+f"(c[1]), "+f"(c[2]), "+f"(c[3])
        : "r"(a[0]), "r"(a[1]), "r"(a[2]), "r"(a[3]), "r"(b[0]), "r"(b[1]));
}

// ---------------- smem layout (32-bit words) ----------------
#define APW 12                 // A row pitch: 8 f16x2 words + 4 pad (banks 12g+t distinct)
#define BPW 136                // B row pitch: 128 words + 8 pad (banks 8t+g distinct)
#define OFF_BW (256*APW)       // 3072 : B stage after A stage (stage total 4160 words)
#define YP 257                 // Ys pitch
#define OFF_S (128*257)        // 32896 : stats sum (256)
#define OFF_Q (OFF_S + 256)
#define OFF_W (OFF_Q + 256)    // interp weights (384)
#define OFF_I (OFF_W + 384)    // interp indices (384)
#define SMEMF (OFF_I + 384)    // 34176 words
#define SMEM_BYTES (SMEMF * 4) // 136704 bytes

// ---------------- small kernels ----------------
__global__ void zero_stats_kernel() {
    int t = threadIdx.x;
    g_s1[t] = 0.f; g_q1[t] = 0.f; g_s2[t] = 0.f; g_q2[t] = 0.f;
}

__global__ void knn_kernel(const float* __restrict__ unknown,
                           const float* __restrict__ known) {
    __shared__ float ks[M_*3];
    int b = blockIdx.y;
    const float* kb = known + (size_t)b * M_ * 3;
    for (int i = threadIdx.x; i < M_*3; i += blockDim.x) ks[i] = kb[i];
    __syncthreads();
    int n = blockIdx.x * blockDim.x + threadIdx.x;
    const float* u = unknown + ((size_t)b * N_ + n) * 3;
    float ux = u[0], uy = u[1], uz = u[2];
    float d0 = 3.4e38f, d1 = 3.4e38f, d2 = 3.4e38f;
    int   i0 = 0, i1 = 0, i2 = 0;
    for (int m = 0; m < M_; m++) {
        float dx = ux - ks[m*3], dy = uy - ks[m*3+1], dz = uz - ks[m*3+2];
        float d  = dx*dx + dy*dy + dz*dz;
        if (d < d2) {
            if (d < d0)      { d2=d1; i2=i1; d1=d0; i1=i0; d0=d; i0=m; }
            else if (d < d1) { d2=d1; i2=i1; d1=d;  i1=m; }
            else             { d2=d;  i2=m; }
        }
    }
    float r0 = 1.f / (sqrtf(fmaxf(d0, 0.f)) + 1e-8f);
    float r1 = 1.f / (sqrtf(fmaxf(d1, 0.f)) + 1e-8f);
    float r2 = 1.f / (sqrtf(fmaxf(d2, 0.f)) + 1e-8f);
    float inv = 1.f / (r0 + r1 + r2);
    int base = (b * N_ + n) * 3;
    g_idx[base] = i0; g_idx[base+1] = i1; g_idx[base+2] = i2;
    g_w[base] = r0*inv; g_w[base+1] = r1*inv; g_w[base+2] = r2*inv;
}

__global__ void bnfin_kernel(const float* __restrict__ gamma,
                             const float* __restrict__ beta, int which) {
    int t = threadIdx.x;
    float s = which ? g_s2[t] : g_s1[t];
    float q = which ? g_q2[t] : g_q1[t];
    float mean = s * (1.f / CNT_);
    float var  = q * (1.f / CNT_) - mean * mean;
    float sc = gamma[t] * rsqrtf(var + 1e-5f);
    float bi = beta[t] - mean * sc;
    if (which) { g_scale2[t] = sc; g_bias2[t] = bi; }
    else       { g_scale1[t] = sc; g_bias1[t] = bi; }
}

__global__ void out_kernel(float* __restrict__ out) {
    int i = blockIdx.x * blockDim.x + threadIdx.x;
    int o = (i >> 11) & 255;
    float sc = g_scale2[o], bi = g_bias2[o];
    float4 v = ((float4*)out)[i];
    v.x = fmaxf(fmaf(v.x, sc, bi), 0.f);
    v.y = fmaxf(fmaf(v.y, sc, bi), 0.f);
    v.z = fmaxf(fmaf(v.z, sc, bi), 0.f);
    v.w = fmaxf(fmaf(v.w, sc, bi), 0.f);
    ((float4*)out)[i] = v;
}

// ---------------- GEMM core (fp16 m16n8k16) ----------------
// Block tile 256(o) x 128(n), K chunk 16. 8 warps (4 o x 2 n), warp tile 64x64.
// A: As[o][k2] f16x2, pitch APW. B: Bs[k2][n] f16x2 packed across k-pair, pitch BPW.
// Single smem stage, register-pipelined LDG of next chunk during compute.

__device__ __forceinline__ void ldgA(const float* Wsrc, int ws, int c, int tid, float4* ra) {
    const float* s = Wsrc + (size_t)tid * ws + c*16;
    ra[0] = *(const float4*)s;       ra[1] = *(const float4*)(s + 4);
    ra[2] = *(const float4*)(s + 8); ra[3] = *(const float4*)(s + 12);
}
__device__ __forceinline__ void ldgB(const float* X, int cs, int c, int tid,
                                     float4& r0, float4& r1) {
    int k2 = tid >> 5, ng = (tid & 31) * 4;
    const float* s = X + (size_t)(c*16 + 2*k2) * cs + ng;
    r0 = *(const float4*)s;
    r1 = *(const float4*)(s + cs);
}
__device__ __forceinline__ void stsA(unsigned* As, const float4* ra, int tid) {
    unsigned w0[4], w1[4];
    w0[0] = pack2(ra[0].x, ra[0].y); w0[1] = pack2(ra[0].z, ra[0].w);
    w0[2] = pack2(ra[1].x, ra[1].y); w0[3] = pack2(ra[1].z, ra[1].w);
    w1[0] = pack2(ra[2].x, ra[2].y); w1[1] = pack2(ra[2].z, ra[2].w);
    w1[2] = pack2(ra[3].x, ra[3].y); w1[3] = pack2(ra[3].z, ra[3].w);
    *(uint4*)(As + tid*APW)     = *(uint4*)w0;
    *(uint4*)(As + tid*APW + 4) = *(uint4*)w1;
}
__device__ __forceinline__ void stsB(unsigned* Bs, float4 r0, float4 r1, int tid) {
    int k2 = tid >> 5, ng = (tid & 31) * 4;
    unsigned w[4];
    w[0] = pack2(r0.x, r1.x); w[1] = pack2(r0.y, r1.y);
    w[2] = pack2(r0.z, r1.z); w[3] = pack2(r0.w, r1.w);
    *(uint4*)(Bs + k2*BPW + ng) = *(uint4*)w;
}

__device__ __forceinline__ void frag_mma16(const unsigned* As, const unsigned* Bs,
                                           int wo, int wn, int g, int t,
                                           float acc[4][8][4]) {
    unsigned af[4][4], bf[8][2];
    #pragma unroll
    for (int mi = 0; mi < 4; mi++) {
        int row = wo*64 + mi*16 + g;
        af[mi][0] = As[row*APW + t];
        af[mi][1] = As[(row+8)*APW + t];
        af[mi][2] = As[row*APW + t + 4];
        af[mi][3] = As[(row+8)*APW + t + 4];
    }
    #pragma unroll
    for (int ni = 0; ni < 8; ni++) {
        int nb = wn*64 + ni*8 + g;
        bf[ni][0] = Bs[t*BPW + nb];
        bf[ni][1] = Bs[(t+4)*BPW + nb];
    }
    #pragma unroll
    for (int mi = 0; mi < 4; mi++)
        #pragma unroll
        for (int ni = 0; ni < 8; ni++)
            hmma16(acc[mi][ni], af[mi], bf[ni]);
}

__device__ __forceinline__ void mainloop16(float* sm, const float* Wsrc, int ws,
                                           const float* Xsrc, int cs,
                                           float acc[4][8][4]) {
    int tid = threadIdx.x, lane = tid & 31, w = tid >> 5;
    int wo = w >> 1, wn = w & 1, g = lane >> 2, t = lane & 3;
    unsigned* As = (unsigned*)sm;
    unsigned* Bs = As + OFF_BW;
    float4 ra[4], rb0, rb1;
    ldgA(Wsrc, ws, 0, tid, ra);
    ldgB(Xsrc, cs, 0, tid, rb0, rb1);
    for (int c = 0; c < 16; c++) {
        stsA(As, ra, tid);
        stsB(Bs, rb0, rb1, tid);
        __syncthreads();
        if (c < 15) {                       // prefetch next chunk during compute
            ldgA(Wsrc, ws, c+1, tid, ra);
            ldgB(Xsrc, cs, c+1, tid, rb0, rb1);
        }
        frag_mma16(As, Bs, wo, wn, g, t, acc);
        __syncthreads();
    }
}

__device__ __forceinline__ void acc_to_ys(float* sm, float acc[4][8][4],
                                          int wo, int wn, int g, int t) {
    #pragma unroll
    for (int mi = 0; mi < 4; mi++)
        #pragma unroll
        for (int ni = 0; ni < 8; ni++) {
            int orow = wo*64 + mi*16 + g;
            int ncol = wn*64 + ni*8 + 2*t;
            sm[ncol*YP + orow]       = acc[mi][ni][0];
            sm[(ncol+1)*YP + orow]   = acc[mi][ni][1];
            sm[ncol*YP + orow+8]     = acc[mi][ni][2];
            sm[(ncol+1)*YP + orow+8] = acc[mi][ni][3];
        }
}

// ---------------- gemmG: G[z][m][o] = W1a @ kf ----------------
__global__ __launch_bounds__(256, 1) void gemmG(const float* __restrict__ kf,
                                                const float* __restrict__ W1) {
    extern __shared__ float sm[];
    int tid = threadIdx.x, lane = tid & 31, w = tid >> 5;
    int z = blockIdx.y, b = z >> 2, r = z & 3;
    int m0 = blockIdx.x * 128;
    float acc[4][8][4] = {};
    const float* X = kf + (size_t)b * (C_*NR_*M_) + (size_t)r * M_ + m0;
    mainloop16(sm, W1, 512, X, NR_*M_, acc);
    int wo = w >> 1, wn = w & 1, g = lane >> 2, t = lane & 3;
    acc_to_ys(sm, acc, wo, wn, g, t);
    __syncthreads();
    float* Gz = g_G + ((size_t)z * M_ + m0) * C_;
    for (int it = 0; it < 16; it++) {
        int m = it*8 + w;
        #pragma unroll
        for (int j = 0; j < 8; j++) {
            int o = lane + 32*j;
            Gz[(size_t)m * C_ + o] = sm[m*YP + o];
        }
    }
}

// ---------------- gemmY1: y1[z][c][n] = W1b@uf + gather(G); BN1 stats ----------------
__global__ __launch_bounds__(256, 1) void gemmY1(const float* __restrict__ uf,
                                                 const float* __restrict__ W1) {
    extern __shared__ float sm[];
    int tid = threadIdx.x, lane = tid & 31, w = tid >> 5;
    int z = blockIdx.y, b = z >> 2, r = z & 3;
    int n0 = blockIdx.x * 128;
    for (int l = tid; l < 384; l += 256) {
        sm[OFF_W + l]         = g_w  [(b * N_ + n0) * 3 + l];
        ((int*)sm)[OFF_I + l] = g_idx[(b * N_ + n0) * 3 + l];
    }
    sm[OFF_S + tid] = 0.f; sm[OFF_Q + tid] = 0.f;
    float acc[4][8][4] = {};
    const float* X = uf + (size_t)b * (C_*NR_*N_) + (size_t)r * N_ + n0;
    mainloop16(sm, W1 + 256, 512, X, NR_*N_, acc);
    int wo = w >> 1, wn = w & 1, g = lane >> 2, t = lane & 3;
    acc_to_ys(sm, acc, wo, wn, g, t);
    __syncthreads();
    // gather + BN1 stats (warp-per-n, lane-per-o)
    const float* Gz = g_G + (size_t)z * M_ * C_;
    float s8[8] = {}, q8[8] = {};
    for (int it = 0; it < 16; it++) {
        int n = it*8 + w;
        float w0 = sm[OFF_W + n*3], w1 = sm[OFF_W + n*3+1], w2 = sm[OFF_W + n*3+2];
        const float* G0 = Gz + (size_t)((int*)sm)[OFF_I + n*3]     * C_;
        const float* G1 = Gz + (size_t)((int*)sm)[OFF_I + n*3 + 1] * C_;
        const float* G2 = Gz + (size_t)((int*)sm)[OFF_I + n*3 + 2] * C_;
        #pragma unroll
        for (int j = 0; j < 8; j++) {
            int o = lane + 32*j;
            float v = sm[n*YP + o] + w0*G0[o] + w1*G1[o] + w2*G2[o];
            sm[n*YP + o] = v;
            s8[j] += v; q8[j] += v*v;
        }
    }
    #pragma unroll
    for (int j = 0; j < 8; j++) {
        atomicAdd(&sm[OFF_S + lane + 32*j], s8[j]);
        atomicAdd(&sm[OFF_Q + lane + 32*j], q8[j]);
    }
    __syncthreads();
    atomicAdd(&g_s1[tid], sm[OFF_S + tid]);
    atomicAdd(&g_q1[tid], sm[OFF_Q + tid]);
    float* y1z = g_y1 + (size_t)z * C_ * N_ + n0;
    for (int it = 0; it < 32; it++) {
        int o = it*8 + w;
        #pragma unroll
        for (int j = 0; j < 4; j++) {
            int n = lane + 32*j;
            y1z[(size_t)o * N_ + n] = sm[n*YP + o];
        }
    }
}

// ---------------- gemmZ: out = W2 @ relu(bn1(y1)); BN2 stats ----------------
__global__ __launch_bounds__(256, 1) void gemmZ(const float* __restrict__ W2,
                                                float* __restrict__ out) {
    extern __shared__ float sm[];
    int tid = threadIdx.x, lane = tid & 31, w = tid >> 5;
    int z = blockIdx.y, b = z >> 2, r = z & 3;
    int n0 = blockIdx.x * 128;
    sm[OFF_S + tid] = 0.f; sm[OFF_Q + tid] = 0.f;
    float acc[4][8][4] = {};
    const float* y1z = g_y1 + (size_t)z * C_ * N_ + n0;
    int wo = w >> 1, wn = w & 1, g = lane >> 2, t = lane & 3;
    int k2 = tid >> 5;
    unsigned* As = (unsigned*)sm;
    unsigned* Bs = As + OFF_BW;

    float4 ra[4], rb0, rb1;
    ldgA(W2, 256, 0, tid, ra);
    ldgB(y1z, N_, 0, tid, rb0, rb1);
    for (int c = 0; c < 16; c++) {
        // BN1 + ReLU fused into the f16 pack
        {
            float sc0 = g_scale1[c*16 + 2*k2],     bi0 = g_bias1[c*16 + 2*k2];
            float sc1 = g_scale1[c*16 + 2*k2 + 1], bi1 = g_bias1[c*16 + 2*k2 + 1];
            float4 v0 = rb0, v1 = rb1;
            v0.x = fmaxf(fmaf(v0.x, sc0, bi0), 0.f); v0.y = fmaxf(fmaf(v0.y, sc0, bi0), 0.f);
            v0.z = fmaxf(fmaf(v0.z, sc0, bi0), 0.f); v0.w = fmaxf(fmaf(v0.w, sc0, bi0), 0.f);
            v1.x = fmaxf(fmaf(v1.x, sc1, bi1), 0.f); v1.y = fmaxf(fmaf(v1.y, sc1, bi1), 0.f);
            v1.z = fmaxf(fmaf(v1.z, sc1, bi1), 0.f); v1.w = fmaxf(fmaf(v1.w, sc1, bi1), 0.f);
            stsB(Bs, v0, v1, tid);
        }
        stsA(As, ra, tid);
        __syncthreads();
        if (c < 15) {
            ldgA(W2, 256, c+1, tid, ra);
            ldgB(y1z, N_, c+1, tid, rb0, rb1);
        }
        frag_mma16(As, Bs, wo, wn, g, t, acc);
        __syncthreads();
    }

    // BN2 stats from pre-BN accumulators
    {
        float s8[8] = {}, q8[8] = {};
        #pragma unroll
        for (int mi = 0; mi < 4; mi++)
            #pragma unroll
            for (int ni = 0; ni < 8; ni++) {
                float a0 = acc[mi][ni][0], a1 = acc[mi][ni][1];
                float a2 = acc[mi][ni][2], a3 = acc[mi][ni][3];
                s8[mi*2]   += a0 + a1;  q8[mi*2]   += a0*a0 + a1*a1;
                s8[mi*2+1] += a2 + a3;  q8[mi*2+1] += a2*a2 + a3*a3;
            }
        #pragma unroll
        for (int mi = 0; mi < 4; mi++) {
            int orow = wo*64 + mi*16 + g;
            atomicAdd(&sm[OFF_S + orow],     s8[mi*2]);
            atomicAdd(&sm[OFF_Q + orow],     q8[mi*2]);
            atomicAdd(&sm[OFF_S + orow + 8], s8[mi*2+1]);
            atomicAdd(&sm[OFF_Q + orow + 8], q8[mi*2+1]);
        }
    }
    __syncthreads();
    atomicAdd(&g_s2[tid], sm[OFF_S + tid]);
    atomicAdd(&g_q2[tid], sm[OFF_Q + tid]);
    acc_to_ys(sm, acc, wo, wn, g, t);
    __syncthreads();
    float* ob = out + ((size_t)b * 256 * 4) * 2048 + (size_t)r * 2048 + n0;
    for (int it = 0; it < 32; it++) {
        int o = it*8 + w;
        #pragma unroll
        for (int j = 0; j < 4; j++) {
            int n = lane + 32*j;
            ob[(size_t)o * (4*2048) + n] = sm[n*YP + o];
        }
    }
}

// ---------------- launch ----------------
extern "C" void kernel_launch(void* const* d_in, const int* in_sizes, int n_in,
                              void* d_out, int out_size) {
    const float* unknown = (const float*)d_in[0];
    const float* known   = (const float*)d_in[1];
    const float* uf      = (const float*)d_in[2];
    const float* kf      = (const float*)d_in[3];
    const float* W1      = (const float*)d_in[4];
    const float* g1      = (const float*)d_in[5];
    const float* b1      = (const float*)d_in[6];
    const float* W2      = (const float*)d_in[7];
    const float* g2      = (const float*)d_in[8];
    const float* b2      = (const float*)d_in[9];
    float* out = (float*)d_out;

    static int inited = 0;
    if (!inited) {
        cudaFuncSetAttribute(gemmG,  cudaFuncAttributeMaxDynamicSharedMemorySize, SMEM_BYTES);
        cudaFuncSetAttribute(gemmY1, cudaFuncAttributeMaxDynamicSharedMemorySize, SMEM_BYTES);
        cudaFuncSetAttribute(gemmZ,  cudaFuncAttributeMaxDynamicSharedMemorySize, SMEM_BYTES);
        inited = 1;
    }

    zero_stats_kernel<<<1, 256>>>();
    knn_kernel<<<dim3(N_/256, B_), 256>>>(unknown, known);
    gemmG<<<dim3(M_/128, B_*NR_), 256, SMEM_BYTES>>>(kf, W1);
    gemmY1<<<dim3(N_/128, B_*NR_), 256, SMEM_BYTES>>>(uf, W1);
    bnfin_kernel<<<1, 256>>>(g1, b1, 0);
    gemmZ<<<dim3(N_/128, B_*NR_), 256, SMEM_BYTES>>>(W2, out);
    bnfin_kernel<<<1, 256>>>(g2, b2, 1);
    out_kernel<<<(B_*256*NR_*N_/4) / 256, 256>>>(out);
}

// round 15
// speedup vs baseline: 1.3404x; 1.2703x over previous
#include <cuda_runtime.h>
#include <cuda_fp16.h>
#include <math.h>
#include <stdint.h>

#define B_   8
#define N_   2048
#define M_   512
#define C_   256
#define NR_  4
#define CNT_ (B_*NR_*N_)

// ---------------- scratch ----------------
__device__ float g_G [B_*NR_*M_*C_];   // [z][m][o] o-contiguous
__device__ float g_y1[B_*NR_*C_*N_];   // [z][c][n] n-contiguous
__device__ int   g_idx[B_*N_*3];
__device__ float g_w  [B_*N_*3];
__device__ float g_s1[C_], g_q1[C_], g_s2[C_], g_q2[C_];
__device__ float g_scale1[C_], g_bias1[C_], g_scale2[C_], g_bias2[C_];
__device__ int   g_tk[4];              // work-stealing tickets (G, Y1, Z)

// ---------------- helpers ----------------
__device__ __forceinline__ unsigned pack2(float lo, float hi) {
    __half2 h = __floats2half2_rn(lo, hi);
    return *reinterpret_cast<unsigned*>(&h);
}
__device__ __forceinline__ void hmma16(float* c, const unsigned* a, const unsigned* b) {
    asm volatile("mma.sync.aligned.m16n8k16.row.col.f32.f16.f16.f32 "
        "{%0,%1,%2,%3}, {%4,%5,%6,%7}, {%8,%9}, {%0,%1,%2,%3};"
        : "+f"(c[0]), "+f"(c[1]), "+f"(c[2]), "+f"(c[3])
        : "r"(a[0]), "r"(a[1]), "r"(a[2]), "r"(a[3]), "r"(b[0]), "r"(b[1]));
}

// ---------------- smem layout (32-bit words), per CTA ----------------
#define APW 12                 // A row pitch: 8 f16x2 words + 4 pad
#define BPW 136                // B row pitch: 128 words + 8 pad
#define OFF_BW (128*APW)       // 1536 : B stage after A stage (stage = 2624 w, aliases Ys)
#define YP  129                // Ys pitch (odd)
#define OFF_S (128*YP)         // 16512
#define OFF_Q (OFF_S + 128)
#define OFF_W (OFF_Q + 128)
#define OFF_I (OFF_W + 384)
#define OFF_T (OFF_I + 384)    // s_tile
#define SMEMF (OFF_T + 8)
#define SMEM_BYTES (SMEMF * 4) // ~70.2 KB

#define NT_Y (2*16*32)         // 1024 tiles (o2 x n16 x z32)
#define NT_G (2*4*32)          // 256 tiles
#define GRID_P 296

// ---------------- small kernels ----------------
__global__ void zero_stats_kernel() {
    int t = threadIdx.x;
    g_s1[t] = 0.f; g_q1[t] = 0.f; g_s2[t] = 0.f; g_q2[t] = 0.f;
    if (t < 4) g_tk[t] = 0;
}

__global__ void knn_kernel(const float* __restrict__ unknown,
                           const float* __restrict__ known) {
    __shared__ float ks[M_*3];
    int b = blockIdx.y;
    const float* kb = known + (size_t)b * M_ * 3;
    for (int i = threadIdx.x; i < M_*3; i += blockDim.x) ks[i] = kb[i];
    __syncthreads();
    int n = blockIdx.x * blockDim.x + threadIdx.x;
    const float* u = unknown + ((size_t)b * N_ + n) * 3;
    float ux = u[0], uy = u[1], uz = u[2];
    float d0 = 3.4e38f, d1 = 3.4e38f, d2 = 3.4e38f;
    int   i0 = 0, i1 = 0, i2 = 0;
    for (int m = 0; m < M_; m++) {
        float dx = ux - ks[m*3], dy = uy - ks[m*3+1], dz = uz - ks[m*3+2];
        float d  = dx*dx + dy*dy + dz*dz;
        if (d < d2) {
            if (d < d0)      { d2=d1; i2=i1; d1=d0; i1=i0; d0=d; i0=m; }
            else if (d < d1) { d2=d1; i2=i1; d1=d;  i1=m; }
            else             { d2=d;  i2=m; }
        }
    }
    float r0 = 1.f / (sqrtf(fmaxf(d0, 0.f)) + 1e-8f);
    float r1 = 1.f / (sqrtf(fmaxf(d1, 0.f)) + 1e-8f);
    float r2 = 1.f / (sqrtf(fmaxf(d2, 0.f)) + 1e-8f);
    float inv = 1.f / (r0 + r1 + r2);
    int base = (b * N_ + n) * 3;
    g_idx[base] = i0; g_idx[base+1] = i1; g_idx[base+2] = i2;
    g_w[base] = r0*inv; g_w[base+1] = r1*inv; g_w[base+2] = r2*inv;
}

__global__ void bnfin_kernel(const float* __restrict__ gamma,
                             const float* __restrict__ beta, int which) {
    int t = threadIdx.x;
    float s = which ? g_s2[t] : g_s1[t];
    float q = which ? g_q2[t] : g_q1[t];
    float mean = s * (1.f / CNT_);
    float var  = q * (1.f / CNT_) - mean * mean;
    float sc = gamma[t] * rsqrtf(var + 1e-5f);
    float bi = beta[t] - mean * sc;
    if (which) { g_scale2[t] = sc; g_bias2[t] = bi; }
    else       { g_scale1[t] = sc; g_bias1[t] = bi; }
}

__global__ void out_kernel(float* __restrict__ out) {
    int i = blockIdx.x * blockDim.x + threadIdx.x;
    int o = (i >> 11) & 255;
    float sc = g_scale2[o], bi = g_bias2[o];
    float4 v = ((float4*)out)[i];
    v.x = fmaxf(fmaf(v.x, sc, bi), 0.f);
    v.y = fmaxf(fmaf(v.y, sc, bi), 0.f);
    v.z = fmaxf(fmaf(v.z, sc, bi), 0.f);
    v.w = fmaxf(fmaf(v.w, sc, bi), 0.f);
    ((float4*)out)[i] = v;
}

// ---------------- GEMM core (fp16 m16n8k16, tile 128o x 128n) ----------------
// 8 warps as (wo 0..3)x(wn 0..1); warp tile 32o x 64n = 2 mtiles x 8 ntiles.
// A: As[o(128)][APW] f16x2. B: Bs[k2(8)][BPW] f16x2 (k-pair packed).

__device__ __forceinline__ void ldgA(const float* W, int ws, int o0, int c, int tid,
                                     float4* ra) {
    const float* s = W + (size_t)(o0 + (tid & 127)) * ws + c*16 + (tid >> 7) * 8;
    ra[0] = *(const float4*)s; ra[1] = *(const float4*)(s + 4);
}
__device__ __forceinline__ void stsA(unsigned* As, const float4* ra, int tid) {
    unsigned w0[4];
    w0[0] = pack2(ra[0].x, ra[0].y); w0[1] = pack2(ra[0].z, ra[0].w);
    w0[2] = pack2(ra[1].x, ra[1].y); w0[3] = pack2(ra[1].z, ra[1].w);
    *(uint4*)(As + (tid & 127)*APW + (tid >> 7) * 4) = *(uint4*)w0;
}
__device__ __forceinline__ void ldgB(const float* X, int cs, int c, int tid,
                                     float4& r0, float4& r1) {
    int k2 = tid >> 5, ng = (tid & 31) * 4;
    const float* s = X + (size_t)(c*16 + 2*k2) * cs + ng;
    r0 = *(const float4*)s;
    r1 = *(const float4*)(s + cs);
}
__device__ __forceinline__ void stsB(unsigned* Bs, float4 r0, float4 r1, int tid) {
    int k2 = tid >> 5, ng = (tid & 31) * 4;
    unsigned w[4];
    w[0] = pack2(r0.x, r1.x); w[1] = pack2(r0.y, r1.y);
    w[2] = pack2(r0.z, r1.z); w[3] = pack2(r0.w, r1.w);
    *(uint4*)(Bs + k2*BPW + ng) = *(uint4*)w;
}

__device__ __forceinline__ void frag_mma16(const unsigned* As, const unsigned* Bs,
                                           int wo, int wn, int g, int t,
                                           float acc[2][8][4]) {
    unsigned af[2][4], bf[8][2];
    #pragma unroll
    for (int mi = 0; mi < 2; mi++) {
        int row = wo*32 + mi*16 + g;
        af[mi][0] = As[row*APW + t];
        af[mi][1] = As[(row+8)*APW + t];
        af[mi][2] = As[row*APW + t + 4];
        af[mi][3] = As[(row+8)*APW + t + 4];
    }
    #pragma unroll
    for (int ni = 0; ni < 8; ni++) {
        int nb = wn*64 + ni*8 + g;
        bf[ni][0] = Bs[t*BPW + nb];
        bf[ni][1] = Bs[(t+4)*BPW + nb];
    }
    #pragma unroll
    for (int mi = 0; mi < 2; mi++)
        #pragma unroll
        for (int ni = 0; ni < 8; ni++)
            hmma16(acc[mi][ni], af[mi], bf[ni]);
}

__device__ __forceinline__ void mainloop16(float* sm, const float* W, int ws, int o0,
                                           const float* X, int cs,
                                           float acc[2][8][4]) {
    int tid = threadIdx.x, lane = tid & 31, w = tid >> 5;
    int wo = w >> 1, wn = w & 1, g = lane >> 2, t = lane & 3;
    unsigned* As = (unsigned*)sm;
    unsigned* Bs = As + OFF_BW;
    float4 ra[2], rb0, rb1;
    ldgA(W, ws, o0, 0, tid, ra);
    ldgB(X, cs, 0, tid, rb0, rb1);
    for (int c = 0; c < 16; c++) {
        stsA(As, ra, tid);
        stsB(Bs, rb0, rb1, tid);
        __syncthreads();
        if (c < 15) {
            ldgA(W, ws, o0, c+1, tid, ra);
            ldgB(X, cs, c+1, tid, rb0, rb1);
        }
        frag_mma16(As, Bs, wo, wn, g, t, acc);
        __syncthreads();
    }
}

__device__ __forceinline__ void acc_to_ys(float* sm, float acc[2][8][4],
                                          int wo, int wn, int g, int t) {
    #pragma unroll
    for (int mi = 0; mi < 2; mi++)
        #pragma unroll
        for (int ni = 0; ni < 8; ni++) {
            int orow = wo*32 + mi*16 + g;
            int ncol = wn*64 + ni*8 + 2*t;
            sm[ncol*YP + orow]       = acc[mi][ni][0];
            sm[(ncol+1)*YP + orow]   = acc[mi][ni][1];
            sm[ncol*YP + orow+8]     = acc[mi][ni][2];
            sm[(ncol+1)*YP + orow+8] = acc[mi][ni][3];
        }
}

// ---------------- gemmG: G[z][m][o] = W1a @ kf (persistent tiles) ----------------
__global__ __launch_bounds__(256, 2) void gemmG(const float* __restrict__ kf,
                                                const float* __restrict__ W1) {
    extern __shared__ float sm[];
    int tid = threadIdx.x, lane = tid & 31, w = tid >> 5;
    int wo = w >> 1, wn = w & 1, g = lane >> 2, t = lane & 3;
    volatile int* s_tile = (volatile int*)(sm + OFF_T);
    for (;;) {
        if (tid == 0) *s_tile = atomicAdd(&g_tk[0], 1);
        __syncthreads();
        int tile = *s_tile;
        if (tile >= NT_G) break;
        int z = tile >> 3, o0 = ((tile >> 2) & 1) * 128, m0 = (tile & 3) * 128;
        int b = z >> 2, r = z & 3;
        float acc[2][8][4] = {};
        const float* X = kf + (size_t)b * (C_*NR_*M_) + (size_t)r * M_ + m0;
        mainloop16(sm, W1, 512, o0, X, NR_*M_, acc);
        acc_to_ys(sm, acc, wo, wn, g, t);
        __syncthreads();
        float* Gz = g_G + ((size_t)z * M_ + m0) * C_ + o0;
        for (int it = 0; it < 16; it++) {
            int m = it*8 + w;
            #pragma unroll
            for (int j = 0; j < 4; j++) {
                int o = lane + 32*j;
                Gz[(size_t)m * C_ + o] = sm[m*YP + o];
            }
        }
        __syncthreads();
    }
}

// ---------------- gemmY1: y1 = W1b@uf + gather(G); BN1 stats ----------------
__global__ __launch_bounds__(256, 2) void gemmY1(const float* __restrict__ uf,
                                                 const float* __restrict__ W1) {
    extern __shared__ float sm[];
    int tid = threadIdx.x, lane = tid & 31, w = tid >> 5;
    int wo = w >> 1, wn = w & 1, g = lane >> 2, t = lane & 3;
    volatile int* s_tile = (volatile int*)(sm + OFF_T);
    for (;;) {
        if (tid == 0) *s_tile = atomicAdd(&g_tk[1], 1);
        __syncthreads();
        int tile = *s_tile;
        if (tile >= NT_Y) break;
        int z = tile >> 5, o0 = ((tile >> 4) & 1) * 128, n0 = (tile & 15) * 128;
        int b = z >> 2, r = z & 3;
        float acc[2][8][4] = {};
        const float* X = uf + (size_t)b * (C_*NR_*N_) + (size_t)r * N_ + n0;
        mainloop16(sm, W1 + 256, 512, o0, X, NR_*N_, acc);
        acc_to_ys(sm, acc, wo, wn, g, t);
        // load interp data + zero local stats
        for (int l = tid; l < 384; l += 256) {
            sm[OFF_W + l]         = g_w  [(b * N_ + n0) * 3 + l];
            ((int*)sm)[OFF_I + l] = g_idx[(b * N_ + n0) * 3 + l];
        }
        if (tid < 128) { sm[OFF_S + tid] = 0.f; sm[OFF_Q + tid] = 0.f; }
        __syncthreads();
        // gather + BN1 stats (warp-per-n, lane-per-o)
        const float* Gz = g_G + (size_t)z * M_ * C_ + o0;
        float s4[4] = {}, q4[4] = {};
        for (int it = 0; it < 16; it++) {
            int n = it*8 + w;
            float w0 = sm[OFF_W + n*3], w1 = sm[OFF_W + n*3+1], w2 = sm[OFF_W + n*3+2];
            const float* G0 = Gz + (size_t)((int*)sm)[OFF_I + n*3]     * C_;
            const float* G1 = Gz + (size_t)((int*)sm)[OFF_I + n*3 + 1] * C_;
            const float* G2 = Gz + (size_t)((int*)sm)[OFF_I + n*3 + 2] * C_;
            #pragma unroll
            for (int j = 0; j < 4; j++) {
                int o = lane + 32*j;
                float v = sm[n*YP + o] + w0*G0[o] + w1*G1[o] + w2*G2[o];
                sm[n*YP + o] = v;
                s4[j] += v; q4[j] += v*v;
            }
        }
        #pragma unroll
        for (int j = 0; j < 4; j++) {
            atomicAdd(&sm[OFF_S + lane + 32*j], s4[j]);
            atomicAdd(&sm[OFF_Q + lane + 32*j], q4[j]);
        }
        __syncthreads();
        if (tid < 128) {
            atomicAdd(&g_s1[o0 + tid], sm[OFF_S + tid]);
            atomicAdd(&g_q1[o0 + tid], sm[OFF_Q + tid]);
        }
        float* y1z = g_y1 + (size_t)z * C_ * N_ + (size_t)o0 * N_ + n0;
        for (int it = 0; it < 16; it++) {
            int o = it*8 + w;
            #pragma unroll
            for (int j = 0; j < 4; j++) {
                int n = lane + 32*j;
                y1z[(size_t)o * N_ + n] = sm[n*YP + o];
            }
        }
        __syncthreads();
    }
}

// ---------------- gemmZ: out = W2 @ relu(bn1(y1)); BN2 stats ----------------
__global__ __launch_bounds__(256, 2) void gemmZ(const float* __restrict__ W2,
                                                float* __restrict__ out) {
    extern __shared__ float sm[];
    int tid = threadIdx.x, lane = tid & 31, w = tid >> 5;
    int wo = w >> 1, wn = w & 1, g = lane >> 2, t = lane & 3;
    int k2 = tid >> 5;
    unsigned* As = (unsigned*)sm;
    unsigned* Bs = As + OFF_BW;
    volatile int* s_tile = (volatile int*)(sm + OFF_T);
    for (;;) {
        if (tid == 0) *s_tile = atomicAdd(&g_tk[2], 1);
        __syncthreads();
        int tile = *s_tile;
        if (tile >= NT_Y) break;
        int z = tile >> 5, o0 = ((tile >> 4) & 1) * 128, n0 = (tile & 15) * 128;
        int b = z >> 2, r = z & 3;
        float acc[2][8][4] = {};
        const float* y1z = g_y1 + (size_t)z * C_ * N_ + n0;
        float4 ra[2], rb0, rb1;
        ldgA(W2, 256, o0, 0, tid, ra);
        ldgB(y1z, N_, 0, tid, rb0, rb1);
        for (int c = 0; c < 16; c++) {
            {   // BN1 + ReLU fused into f16 pack
                float sc0 = g_scale1[c*16 + 2*k2],     bi0 = g_bias1[c*16 + 2*k2];
                float sc1 = g_scale1[c*16 + 2*k2 + 1], bi1 = g_bias1[c*16 + 2*k2 + 1];
                float4 v0 = rb0, v1 = rb1;
                v0.x = fmaxf(fmaf(v0.x, sc0, bi0), 0.f); v0.y = fmaxf(fmaf(v0.y, sc0, bi0), 0.f);
                v0.z = fmaxf(fmaf(v0.z, sc0, bi0), 0.f); v0.w = fmaxf(fmaf(v0.w, sc0, bi0), 0.f);
                v1.x = fmaxf(fmaf(v1.x, sc1, bi1), 0.f); v1.y = fmaxf(fmaf(v1.y, sc1, bi1), 0.f);
                v1.z = fmaxf(fmaf(v1.z, sc1, bi1), 0.f); v1.w = fmaxf(fmaf(v1.w, sc1, bi1), 0.f);
                stsB(Bs, v0, v1, tid);
            }
            stsA(As, ra, tid);
            __syncthreads();
            if (c < 15) {
                ldgA(W2, 256, o0, c+1, tid, ra);
                ldgB(y1z, N_, c+1, tid, rb0, rb1);
            }
            frag_mma16(As, Bs, wo, wn, g, t, acc);
            __syncthreads();
        }
        // BN2 stats from pre-BN accumulators
        if (tid < 128) { sm[OFF_S + tid] = 0.f; sm[OFF_Q + tid] = 0.f; }
        __syncthreads();
        {
            float s2[2] = {}, q2[2] = {};
            #pragma unroll
            for (int mi = 0; mi < 2; mi++) {
                s2[mi] = 0.f; q2[mi] = 0.f;
                float sb = 0.f, qb = 0.f;
                #pragma unroll
                for (int ni = 0; ni < 8; ni++) {
                    float a0 = acc[mi][ni][0], a1 = acc[mi][ni][1];
                    float a2 = acc[mi][ni][2], a3 = acc[mi][ni][3];
                    s2[mi] += a0 + a1;  q2[mi] += a0*a0 + a1*a1;
                    sb += a2 + a3;      qb += a2*a2 + a3*a3;
                }
                int orow = wo*32 + mi*16 + g;
                atomicAdd(&sm[OFF_S + orow],     s2[mi]);
                atomicAdd(&sm[OFF_Q + orow],     q2[mi]);
                atomicAdd(&sm[OFF_S + orow + 8], sb);
                atomicAdd(&sm[OFF_Q + orow + 8], qb);
            }
        }
        __syncthreads();
        if (tid < 128) {
            atomicAdd(&g_s2[o0 + tid], sm[OFF_S + tid]);
            atomicAdd(&g_q2[o0 + tid], sm[OFF_Q + tid]);
        }
        __syncthreads();
        acc_to_ys(sm, acc, wo, wn, g, t);
        __syncthreads();
        float* ob = out + ((size_t)(b*256 + o0) * 4 + r) * 2048 + n0;
        for (int it = 0; it < 16; it++) {
            int o = it*8 + w;
            #pragma unroll
            for (int j = 0; j < 4; j++) {
                int n = lane + 32*j;
                ob[(size_t)o * (4*2048) + n] = sm[n*YP + o];
            }
        }
        __syncthreads();
    }
}

// ---------------- launch ----------------
extern "C" void kernel_launch(void* const* d_in, const int* in_sizes, int n_in,
                              void* d_out, int out_size) {
    const float* unknown = (const float*)d_in[0];
    const float* known   = (const float*)d_in[1];
    const float* uf      = (const float*)d_in[2];
    const float* kf      = (const float*)d_in[3];
    const float* W1      = (const float*)d_in[4];
    const float* g1      = (const float*)d_in[5];
    const float* b1      = (const float*)d_in[6];
    const float* W2      = (const float*)d_in[7];
    const float* g2      = (const float*)d_in[8];
    const float* b2      = (const float*)d_in[9];
    float* out = (float*)d_out;

    static int inited = 0;
    if (!inited) {
        cudaFuncSetAttribute(gemmG,  cudaFuncAttributeMaxDynamicSharedMemorySize, SMEM_BYTES);
        cudaFuncSetAttribute(gemmY1, cudaFuncAttributeMaxDynamicSharedMemorySize, SMEM_BYTES);
        cudaFuncSetAttribute(gemmZ,  cudaFuncAttributeMaxDynamicSharedMemorySize, SMEM_BYTES);
        inited = 1;
    }

    zero_stats_kernel<<<1, 256>>>();
    knn_kernel<<<dim3(N_/256, B_), 256>>>(unknown, known);
    gemmG<<<GRID_P, 256, SMEM_BYTES>>>(kf, W1);
    gemmY1<<<GRID_P, 256, SMEM_BYTES>>>(uf, W1);
    bnfin_kernel<<<1, 256>>>(g1, b1, 0);
    gemmZ<<<GRID_P, 256, SMEM_BYTES>>>(W2, out);
    bnfin_kernel<<<1, 256>>>(g2, b2, 1);
    out_kernel<<<(B_*256*NR_*N_/4) / 256, 256>>>(out);
}